// round 3
// baseline (speedup 1.0000x reference)
#include <cuda_runtime.h>
#include <math.h>

#define T_TOKENS   8192
#define N_EXPERTS  256
#define HIDDEN_DIM 7168
#define N_GROUP    8
#define GROUP_SIZE 32
#define TOPK_GROUP 4
#define TOP_K      8
#define ROUTED_SCALE 2.5f

// 8 MB fp32 logits scratch
__device__ float g_logits[T_TOKENS * N_EXPERTS];

// ---------------------------------------------------------------------------
// GEMM: logits[T, E] = X[T, H] @ W[E, H]^T   (fp32, FFMA2 packed math)
// BM=64, BN=128, BK=16, 256 threads, per-thread 8(m) x 4(n), m packed in pairs
// ---------------------------------------------------------------------------
#define BM 64
#define BN 128
#define BK 16
#define AS_LD (BM + 4)   // 68 floats per k-row (16B-aligned stride)
#define BS_LD (BN + 4)   // 132 floats per k-row
#define AS_BYTES (BK * AS_LD * 4)
#define BS_BYTES (BK * BS_LD * 4)

#define FMA2(d, a, b) asm volatile("fma.rn.f32x2 %0, %1, %2, %0;" : "+l"(d) : "l"(a), "l"(b))

__global__ __launch_bounds__(256, 2)
void gate_gemm_kernel(const float* __restrict__ X, const float* __restrict__ W) {
    __shared__ float As[2][BK][AS_LD];   // [k][m] (transposed)
    __shared__ float Bs[2][BK][BS_LD];   // [k][n] (transposed)

    const int tid = threadIdx.x;
    const int bm = blockIdx.y * BM;
    const int bn = blockIdx.x * BN;

    const int tx = tid & 31;   // n = tx*4 .. tx*4+3
    const int ty = tid >> 5;   // m = ty*8 .. ty*8+7  (warp-uniform)

    // global load assignments
    const int arow  = tid >> 2;        // 0..63
    const int acol4 = (tid & 3) * 4;   // 0,4,8,12
    const int brow  = tid >> 2;        // 0..63 (and +64)
    const int bcol4 = (tid & 3) * 4;

    const float* Aptr  = X + (size_t)(bm + arow) * HIDDEN_DIM + acol4;
    const float* Bptr0 = W + (size_t)(bn + brow) * HIDDEN_DIM + bcol4;
    const float* Bptr1 = W + (size_t)(bn + brow + 64) * HIDDEN_DIM + bcol4;

    float4 aReg  = *(const float4*)Aptr;
    float4 bReg0 = *(const float4*)Bptr0;
    float4 bReg1 = *(const float4*)Bptr1;

    unsigned long long acc[4][4];
#pragma unroll
    for (int i = 0; i < 4; i++)
#pragma unroll
        for (int j = 0; j < 4; j++) acc[i][j] = 0ULL;

    unsigned sA = (unsigned)__cvta_generic_to_shared(&As[0][0][0]);
    unsigned sB = (unsigned)__cvta_generic_to_shared(&Bs[0][0][0]);

    const int NT = HIDDEN_DIM / BK;   // 448
    int buf = 0;

    for (int kt = 0; kt < NT; kt++) {
        // stage current regs into smem[buf]
        As[buf][acol4 + 0][arow] = aReg.x;
        As[buf][acol4 + 1][arow] = aReg.y;
        As[buf][acol4 + 2][arow] = aReg.z;
        As[buf][acol4 + 3][arow] = aReg.w;
        Bs[buf][bcol4 + 0][brow] = bReg0.x;
        Bs[buf][bcol4 + 1][brow] = bReg0.y;
        Bs[buf][bcol4 + 2][brow] = bReg0.z;
        Bs[buf][bcol4 + 3][brow] = bReg0.w;
        Bs[buf][bcol4 + 0][brow + 64] = bReg1.x;
        Bs[buf][bcol4 + 1][brow + 64] = bReg1.y;
        Bs[buf][bcol4 + 2][brow + 64] = bReg1.z;
        Bs[buf][bcol4 + 3][brow + 64] = bReg1.w;
        __syncthreads();

        // prefetch next tile into regs (latency overlapped with compute)
        if (kt + 1 < NT) {
            Aptr += BK; Bptr0 += BK; Bptr1 += BK;
            aReg  = *(const float4*)Aptr;
            bReg0 = *(const float4*)Bptr0;
            bReg1 = *(const float4*)Bptr1;
        }

        unsigned aAdr = sA + (buf ? AS_BYTES : 0) + (unsigned)(ty * 8) * 4u;
        unsigned bAdr = sB + (buf ? BS_BYTES : 0) + (unsigned)(tx * 4) * 4u;

#pragma unroll
        for (int k = 0; k < BK; k++) {
            unsigned long long a01, a23, a45, a67;
            asm volatile("ld.shared.v2.u64 {%0,%1}, [%2];"
                         : "=l"(a01), "=l"(a23) : "r"(aAdr));
            asm volatile("ld.shared.v2.u64 {%0,%1}, [%2];"
                         : "=l"(a45), "=l"(a67) : "r"(aAdr + 16));
            float b0, b1, b2, b3;
            asm volatile("ld.shared.v4.f32 {%0,%1,%2,%3}, [%4];"
                         : "=f"(b0), "=f"(b1), "=f"(b2), "=f"(b3) : "r"(bAdr));
            unsigned long long bb0, bb1, bb2, bb3;
            asm volatile("mov.b64 %0, {%1,%1};" : "=l"(bb0) : "f"(b0));
            asm volatile("mov.b64 %0, {%1,%1};" : "=l"(bb1) : "f"(b1));
            asm volatile("mov.b64 %0, {%1,%1};" : "=l"(bb2) : "f"(b2));
            asm volatile("mov.b64 %0, {%1,%1};" : "=l"(bb3) : "f"(b3));

            FMA2(acc[0][0], a01, bb0); FMA2(acc[0][1], a01, bb1);
            FMA2(acc[0][2], a01, bb2); FMA2(acc[0][3], a01, bb3);
            FMA2(acc[1][0], a23, bb0); FMA2(acc[1][1], a23, bb1);
            FMA2(acc[1][2], a23, bb2); FMA2(acc[1][3], a23, bb3);
            FMA2(acc[2][0], a45, bb0); FMA2(acc[2][1], a45, bb1);
            FMA2(acc[2][2], a45, bb2); FMA2(acc[2][3], a45, bb3);
            FMA2(acc[3][0], a67, bb0); FMA2(acc[3][1], a67, bb1);
            FMA2(acc[3][2], a67, bb2); FMA2(acc[3][3], a67, bb3);

            aAdr += AS_LD * 4;
            bAdr += BS_LD * 4;
        }
        buf ^= 1;
        __syncthreads();
    }

    // epilogue: unpack pairs (lo = even m, hi = odd m) and store logits
    float* dst = g_logits + (size_t)(bm + ty * 8) * N_EXPERTS + bn + tx * 4;
#pragma unroll
    for (int ip = 0; ip < 4; ip++) {
        float* r0 = dst + (size_t)(2 * ip) * N_EXPERTS;
        float* r1 = r0 + N_EXPERTS;
#pragma unroll
        for (int j = 0; j < 4; j++) {
            float lo, hi;
            asm volatile("mov.b64 {%0,%1}, %2;" : "=f"(lo), "=f"(hi) : "l"(acc[ip][j]));
            r0[j] = lo;
            r1[j] = hi;
        }
    }
}

// ---------------------------------------------------------------------------
// Routing: one warp per token. lane l owns experts [l*8, l*8+8); group g = l/4.
// ---------------------------------------------------------------------------
__global__ __launch_bounds__(256)
void gate_route_kernel(const float* __restrict__ logits,
                       const float* __restrict__ bias,
                       float* __restrict__ out) {
    const unsigned FULL = 0xFFFFFFFFu;
    int token = (blockIdx.x * blockDim.x + threadIdx.x) >> 5;
    int lane = threadIdx.x & 31;
    if (token >= T_TOKENS) return;

    const float* row = logits + (size_t)token * N_EXPERTS;
    float4 l0 = *(const float4*)(row + lane * 8);
    float4 l1 = *(const float4*)(row + lane * 8 + 4);
    float4 c0 = *(const float4*)(bias + lane * 8);
    float4 c1 = *(const float4*)(bias + lane * 8 + 4);

    float lg[8] = {l0.x, l0.y, l0.z, l0.w, l1.x, l1.y, l1.z, l1.w};
    float bi[8] = {c0.x, c0.y, c0.z, c0.w, c1.x, c1.y, c1.z, c1.w};
    float s[8], swb[8];
#pragma unroll
    for (int j = 0; j < 8; j++) {
        s[j] = 1.0f / (1.0f + expf(-lg[j]));
        swb[j] = s[j] + bi[j];
    }

    // lane-local top-2 of biased scores
    float m1 = -INFINITY, m2 = -INFINITY;
#pragma unroll
    for (int j = 0; j < 8; j++) {
        float v = swb[j];
        if (v > m1) { m2 = m1; m1 = v; }
        else if (v > m2) { m2 = v; }
    }
    // merge across the 4 lanes of the group
#pragma unroll
    for (int off = 1; off <= 2; off <<= 1) {
        float o1 = __shfl_xor_sync(FULL, m1, off);
        float o2 = __shfl_xor_sync(FULL, m2, off);
        float hi = fmaxf(m1, o1);
        float lo = fminf(m1, o1);
        m2 = fmaxf(lo, fmaxf(m2, o2));
        m1 = hi;
    }
    float gscore = m1 + m2;   // valid on all lanes of the group

    // gather all 8 group scores; rank my group (tie -> lower group index wins)
    const int g = lane >> 2;
    float gsv[8];
#pragma unroll
    for (int j = 0; j < 8; j++) gsv[j] = __shfl_sync(FULL, gscore, j * 4);
    int rank = 0;
#pragma unroll
    for (int j = 0; j < 8; j++)
        rank += (gsv[j] > gsv[g]) || (gsv[j] == gsv[g] && j < g);
    bool gsel = rank < TOPK_GROUP;

    // masked values (reference: swb * {0,1} mask -> dropped groups become 0.0)
    float mv[8];
#pragma unroll
    for (int j = 0; j < 8; j++) mv[j] = gsel ? swb[j] : 0.0f;

    // iterative top-8 with lower-index tie-break (matches lax.top_k)
    unsigned selmask = 0;
#pragma unroll
    for (int it = 0; it < TOP_K; it++) {
        float bv = mv[0];
        int bj = 0;
#pragma unroll
        for (int j = 1; j < 8; j++)
            if (mv[j] > bv) { bv = mv[j]; bj = j; }
        int bidx = lane * 8 + bj;
#pragma unroll
        for (int off = 16; off > 0; off >>= 1) {
            float ov = __shfl_xor_sync(FULL, bv, off);
            int oi = __shfl_xor_sync(FULL, bidx, off);
            if (ov > bv || (ov == bv && oi < bidx)) { bv = ov; bidx = oi; }
        }
        if ((bidx >> 3) == lane) {
            mv[bidx & 7] = -INFINITY;
            selmask |= 1u << (bidx & 7);
        }
    }

    // normalized scaled output
    float ssum = 0.0f;
#pragma unroll
    for (int j = 0; j < 8; j++)
        if ((selmask >> j) & 1) ssum += s[j];
#pragma unroll
    for (int off = 16; off > 0; off >>= 1)
        ssum += __shfl_xor_sync(FULL, ssum, off);
    float inv = ROUTED_SCALE / (ssum + 1e-20f);

    float o[8];
#pragma unroll
    for (int j = 0; j < 8; j++)
        o[j] = ((selmask >> j) & 1) ? s[j] * inv : 0.0f;

    float* orow = out + (size_t)token * N_EXPERTS + lane * 8;
    *(float4*)(orow) = make_float4(o[0], o[1], o[2], o[3]);
    *(float4*)(orow + 4) = make_float4(o[4], o[5], o[6], o[7]);
}

// ---------------------------------------------------------------------------
extern "C" void kernel_launch(void* const* d_in, const int* in_sizes, int n_in,
                              void* d_out, int out_size) {
    const float* X = (const float*)d_in[0];      // [8192, 7168]
    const float* W = (const float*)d_in[1];      // [256, 7168]
    const float* bias = (const float*)d_in[2];   // [256]
    float* out = (float*)d_out;                  // [8192, 256]

    dim3 ggrid(N_EXPERTS / BN, T_TOKENS / BM);   // (2, 128)
    gate_gemm_kernel<<<ggrid, 256>>>(X, W);

    int rthreads = 256;
    int rblocks = (T_TOKENS * 32) / rthreads;    // 1024
    float* logits_ptr;
    cudaGetSymbolAddress((void**)&logits_ptr, g_logits);
    gate_route_kernel<<<rblocks, rthreads>>>(logits_ptr, bias, out);
}

// round 14
// speedup vs baseline: 1.2339x; 1.2339x over previous
#include <cuda_runtime.h>
#include <cuda_bf16.h>
#include <math.h>
#include <stdint.h>

#define T_TOKENS   8192
#define N_EXPERTS  256
#define HIDDEN_DIM 7168
#define N_GROUP    8
#define TOPK_GROUP 4
#define TOP_K      8
#define ROUTED_SCALE 2.5f

// scratch: fp32 logits + pre-split W (bf16 h/m/l)
__device__ float g_logits[T_TOKENS * N_EXPERTS];
__device__ __nv_bfloat16 g_wh[N_EXPERTS * HIDDEN_DIM];
__device__ __nv_bfloat16 g_wm[N_EXPERTS * HIDDEN_DIM];
__device__ __nv_bfloat16 g_wl[N_EXPERTS * HIDDEN_DIM];

// ---------------------------------------------------------------------------
// helpers
// ---------------------------------------------------------------------------
__device__ __forceinline__ uint32_t smem_to_u32(const void* p) {
    uint32_t a;
    asm("{ .reg .u64 t; cvta.to.shared.u64 t, %1; cvt.u32.u64 %0, t; }" : "=r"(a) : "l"(p));
    return a;
}

// fp32 -> triple bf16 split: h = trunc(x), m = rn(x-h), l = rn(x-h-m).
__device__ __forceinline__ void cvt_split3x4(float4 f, uint2& h, uint2& m, uint2& l) {
    uint32_t xb = __float_as_uint(f.x), yb = __float_as_uint(f.y);
    uint32_t zb = __float_as_uint(f.z), wb = __float_as_uint(f.w);
    h.x = __byte_perm(xb, yb, 0x7632);
    h.y = __byte_perm(zb, wb, 0x7632);
    float r1x = f.x - __uint_as_float(xb & 0xFFFF0000u);
    float r1y = f.y - __uint_as_float(yb & 0xFFFF0000u);
    float r1z = f.z - __uint_as_float(zb & 0xFFFF0000u);
    float r1w = f.w - __uint_as_float(wb & 0xFFFF0000u);
    asm("cvt.rn.bf16x2.f32 %0, %1, %2;" : "=r"(m.x) : "f"(r1y), "f"(r1x));
    asm("cvt.rn.bf16x2.f32 %0, %1, %2;" : "=r"(m.y) : "f"(r1w), "f"(r1z));
    float r2x = r1x - __uint_as_float(m.x << 16);
    float r2y = r1y - __uint_as_float(m.x & 0xFFFF0000u);
    float r2z = r1z - __uint_as_float(m.y << 16);
    float r2w = r1w - __uint_as_float(m.y & 0xFFFF0000u);
    asm("cvt.rn.bf16x2.f32 %0, %1, %2;" : "=r"(l.x) : "f"(r2y), "f"(r2x));
    asm("cvt.rn.bf16x2.f32 %0, %1, %2;" : "=r"(l.y) : "f"(r2w), "f"(r2z));
}

#define LDSM_X4(r, addr) \
    asm volatile("ldmatrix.sync.aligned.m8n8.x4.shared.b16 {%0,%1,%2,%3}, [%4];" \
        : "=r"((r)[0]), "=r"((r)[1]), "=r"((r)[2]), "=r"((r)[3]) : "r"(addr))

#define CP_ASYNC16(dst, src) \
    asm volatile("cp.async.cg.shared.global [%0], [%1], 16;" :: "r"(dst), "l"(src))
#define CP_COMMIT()  asm volatile("cp.async.commit_group;" ::: "memory")
#define CP_WAIT0()   asm volatile("cp.async.wait_group 0;" ::: "memory")

__device__ __forceinline__ void mma16816(float* d, const uint32_t* a, const uint32_t* b) {
    asm volatile(
        "mma.sync.aligned.m16n8k16.row.col.f32.bf16.bf16.f32 "
        "{%0,%1,%2,%3}, {%4,%5,%6,%7}, {%8,%9}, {%0,%1,%2,%3};"
        : "+f"(d[0]), "+f"(d[1]), "+f"(d[2]), "+f"(d[3])
        : "r"(a[0]), "r"(a[1]), "r"(a[2]), "r"(a[3]), "r"(b[0]), "r"(b[1]));
}

__device__ __forceinline__ uint32_t sw128(uint32_t bo) {
    return bo ^ ((bo >> 3) & 0x70u);
}

// ---------------------------------------------------------------------------
// pre-split W into bf16 h/m/l (once per launch; 7.3 MB read)
// ---------------------------------------------------------------------------
__global__ __launch_bounds__(256)
void wsplit_kernel(const float* __restrict__ W) {
    int i = (blockIdx.x * blockDim.x + threadIdx.x) * 4;
    float4 f = *(const float4*)(W + i);
    uint2 h, m, l;
    cvt_split3x4(f, h, m, l);
    *(uint2*)(g_wh + i) = h;
    *(uint2*)(g_wm + i) = m;
    *(uint2*)(g_wl + i) = l;
}

// ---------------------------------------------------------------------------
// GEMM: logits[T,E] = X @ W^T. bf16 mma.sync, 6-pass triple split, fp32 accum.
// The mma accumulator is drained into an FADD-maintained fp32 register sum
// EVERY k16-step (HMMA chain length 6) to suppress biased chained rounding.
// CTA 128x64, 256 threads (8 warps: 2m x 4n, warp tile 64x16).
// K chunk = 64 bf16 (128B SW128 rows), double-buffered SMEM (2 x 72 KB).
// ---------------------------------------------------------------------------
#define GBM 128
#define GBN 64
#define KC 64
#define CHUNKS (HIDDEN_DIM / KC)   // 112
#define OFF_AH 0
#define OFF_AM 16384
#define OFF_AL 32768
#define OFF_BH 49152
#define OFF_BM 57344
#define OFF_BL 65536
#define STAGE_BYTES 73728
#define SMEM_GEMM (2 * STAGE_BYTES)   // 144 KB

__global__ __launch_bounds__(256, 1)
void gate_gemm_mma(const float* __restrict__ X) {
    extern __shared__ char smem[];
    const uint32_t sbase = smem_to_u32(smem);
    const int tid  = threadIdx.x;
    const int wid  = tid >> 5;
    const int lane = tid & 31;
    const int bm = blockIdx.y * GBM;
    const int bn = blockIdx.x * GBN;
    const int wm = (wid & 1) * 64;    // warp m offset (2-way)
    const int wn = (wid >> 1) * 16;   // warp n offset (4-way)

    // ---- producer addressing: A (LDG fp32 -> split -> STS) ----
    const int rbase = tid >> 4;          // A row base (0..15), rows rbase+16i
    const int c16   = tid & 15;          // 4 f32 at col c16*4 -> 8 bytes bf16
    uint32_t aswoff[8];
#pragma unroll
    for (int i = 0; i < 8; i++)
        aswoff[i] = sw128((uint32_t)(rbase + 16 * i) * 128u + (uint32_t)c16 * 8u);
    const float* pA = X + (size_t)(bm + rbase) * HIDDEN_DIM + c16 * 4;

    // ---- producer addressing: B (cp.async of pre-split bf16) ----
    const int browB = tid >> 2;          // B row (0..63)
    const int bq    = tid & 3;           // 32B quarter of the 128B row
    uint32_t bswoff[2];
#pragma unroll
    for (int i = 0; i < 2; i++)
        bswoff[i] = sw128((uint32_t)browB * 128u + (uint32_t)bq * 32u + (uint32_t)i * 16u);
    const size_t bOff = (size_t)(bn + browB) * HIDDEN_DIM + bq * 16;
    const __nv_bfloat16* pBh = g_wh + bOff;
    const __nv_bfloat16* pBm = g_wm + bOff;
    const __nv_bfloat16* pBl = g_wl + bOff;

    // ---- ldmatrix addressing (base/mask form, carry-free) ----
    uint32_t aBase[4], aMask[4];
#pragma unroll
    for (int mt = 0; mt < 4; mt++) {
        uint32_t row = (uint32_t)(wm + mt * 16 + (lane & 15));
        aBase[mt] = row * 128u;
        aMask[mt] = (row << 4) & 0x70u;
    }
    const uint32_t aSel = ((uint32_t)lane >> 4) << 4;   // 0 or 16

    uint32_t bBase, bMask;
    {
        const int grp = lane >> 3;
        uint32_t row = (uint32_t)(wn + (lane & 7) + ((grp >> 1) << 3));
        bBase = row * 128u;
        bMask = (row << 4) & 0x70u;
    }
    const uint32_t bSel = (((uint32_t)lane >> 3) & 1) << 4;   // 0 or 16

    float acc[8][4], tot[8][4];
#pragma unroll
    for (int i = 0; i < 8; i++)
#pragma unroll
        for (int j = 0; j < 4; j++) { acc[i][j] = 0.0f; tot[i][j] = 0.0f; }

    // ---- prologue: fill stage 0 with chunk 0 ----
    {
        float4 aR[8];
#pragma unroll
        for (int i = 0; i < 8; i++)
            aR[i] = *(const float4*)(pA + (size_t)i * 16 * HIDDEN_DIM);
        uint32_t dst = sbase;
#pragma unroll
        for (int i = 0; i < 2; i++) {
            CP_ASYNC16(dst + OFF_BH + bswoff[i], (const char*)(pBh + i * 8));
            CP_ASYNC16(dst + OFF_BM + bswoff[i], (const char*)(pBm + i * 8));
            CP_ASYNC16(dst + OFF_BL + bswoff[i], (const char*)(pBl + i * 8));
        }
        CP_COMMIT();
#pragma unroll
        for (int i = 0; i < 8; i++) {
            uint2 h, m, l;
            cvt_split3x4(aR[i], h, m, l);
            *(uint2*)(smem + OFF_AH + aswoff[i]) = h;
            *(uint2*)(smem + OFF_AM + aswoff[i]) = m;
            *(uint2*)(smem + OFF_AL + aswoff[i]) = l;
        }
        CP_WAIT0();
    }
    __syncthreads();

    // ---- main loop ----
    for (int c = 0; c < CHUNKS; c++) {
        const uint32_t stg = sbase + (uint32_t)(c & 1) * STAGE_BYTES;
        float4 aR[8];
        const int kb = (c + 1) * KC;
        if (c + 1 < CHUNKS) {
            // A (c+1) into regs first (front-batched MLP), then B via cp.async
#pragma unroll
            for (int i = 0; i < 8; i++)
                aR[i] = *(const float4*)(pA + kb + (size_t)i * 16 * HIDDEN_DIM);
            uint32_t dst = sbase + (uint32_t)((c + 1) & 1) * STAGE_BYTES;
#pragma unroll
            for (int i = 0; i < 2; i++) {
                CP_ASYNC16(dst + OFF_BH + bswoff[i], (const char*)(pBh + kb + i * 8));
                CP_ASYNC16(dst + OFF_BM + bswoff[i], (const char*)(pBm + kb + i * 8));
                CP_ASYNC16(dst + OFF_BL + bswoff[i], (const char*)(pBl + kb + i * 8));
            }
            CP_COMMIT();
        }

        // MMA over current stage: 4 k16-steps x 6 passes, drain every k-step
#pragma unroll
        for (int ks = 0; ks < 4; ks++) {
            uint32_t ah[4][4], am[4][4], al[4][4], bh[4], bmr[4], bl[4];
            const uint32_t cbA = aSel | (uint32_t)(ks * 32);
            const uint32_t cbB = bSel | (uint32_t)(ks * 32);
#pragma unroll
            for (int mt = 0; mt < 4; mt++) {
                uint32_t off = aBase[mt] + (cbA ^ aMask[mt]);
                LDSM_X4(ah[mt], stg + OFF_AH + off);
                LDSM_X4(am[mt], stg + OFF_AM + off);
                LDSM_X4(al[mt], stg + OFF_AL + off);
            }
            {
                uint32_t off = bBase + (cbB ^ bMask);
                LDSM_X4(bh,  stg + OFF_BH + off);
                LDSM_X4(bmr, stg + OFF_BM + off);
                LDSM_X4(bl,  stg + OFF_BL + off);
            }
#pragma unroll
            for (int mt = 0; mt < 4; mt++) {
#pragma unroll
                for (int nt = 0; nt < 2; nt++) {
                    float* d = acc[mt * 2 + nt];
                    const uint32_t* Bh = &bh[nt * 2];
                    const uint32_t* Bm = &bmr[nt * 2];
                    const uint32_t* Bl = &bl[nt * 2];
                    mma16816(d, ah[mt], Bh);   // h*h
                    mma16816(d, ah[mt], Bm);   // h*m
                    mma16816(d, am[mt], Bh);   // m*h
                    mma16816(d, am[mt], Bm);   // m*m
                    mma16816(d, ah[mt], Bl);   // h*l
                    mma16816(d, al[mt], Bh);   // l*h
                }
            }
            // drain: RN-add this k-step's partial into the running fp32 sum
            // and reset the mma accumulator (chain length 6 -> negligible bias)
#pragma unroll
            for (int i = 0; i < 8; i++)
#pragma unroll
                for (int j = 0; j < 4; j++) {
                    tot[i][j] += acc[i][j];
                    acc[i][j] = 0.0f;
                }
        }

        if (c + 1 < CHUNKS) {
            char* dst = smem + (size_t)((c + 1) & 1) * STAGE_BYTES;
#pragma unroll
            for (int i = 0; i < 8; i++) {
                uint2 h, m, l;
                cvt_split3x4(aR[i], h, m, l);
                *(uint2*)(dst + OFF_AH + aswoff[i]) = h;
                *(uint2*)(dst + OFF_AM + aswoff[i]) = m;
                *(uint2*)(dst + OFF_AL + aswoff[i]) = l;
            }
            CP_WAIT0();
            __syncthreads();
        }
    }

    // ---- epilogue: write fp32 logits ----
    const int crow = lane >> 2;
    const int ccol = (lane & 3) * 2;
#pragma unroll
    for (int mt = 0; mt < 4; mt++) {
#pragma unroll
        for (int nt = 0; nt < 2; nt++) {
            float* p = g_logits + (size_t)(bm + wm + mt * 16 + crow) * N_EXPERTS
                                + bn + wn + nt * 8 + ccol;
            *(float2*)p = make_float2(tot[mt * 2 + nt][0], tot[mt * 2 + nt][1]);
            *(float2*)(p + 8 * N_EXPERTS) = make_float2(tot[mt * 2 + nt][2], tot[mt * 2 + nt][3]);
        }
    }
}

// ---------------------------------------------------------------------------
// Routing: one warp per token. lane l owns experts [l*8, l*8+8); group g = l/4.
// ---------------------------------------------------------------------------
__global__ __launch_bounds__(256)
void gate_route_kernel(const float* __restrict__ logits,
                       const float* __restrict__ bias,
                       float* __restrict__ out) {
    const unsigned FULL = 0xFFFFFFFFu;
    int token = (blockIdx.x * blockDim.x + threadIdx.x) >> 5;
    int lane = threadIdx.x & 31;
    if (token >= T_TOKENS) return;

    const float* row = logits + (size_t)token * N_EXPERTS;
    float4 l0 = *(const float4*)(row + lane * 8);
    float4 l1 = *(const float4*)(row + lane * 8 + 4);
    float4 c0 = *(const float4*)(bias + lane * 8);
    float4 c1 = *(const float4*)(bias + lane * 8 + 4);

    float lg[8] = {l0.x, l0.y, l0.z, l0.w, l1.x, l1.y, l1.z, l1.w};
    float bi[8] = {c0.x, c0.y, c0.z, c0.w, c1.x, c1.y, c1.z, c1.w};
    float s[8], swb[8];
#pragma unroll
    for (int j = 0; j < 8; j++) {
        s[j] = 1.0f / (1.0f + expf(-lg[j]));
        swb[j] = s[j] + bi[j];
    }

    float m1 = -INFINITY, m2 = -INFINITY;
#pragma unroll
    for (int j = 0; j < 8; j++) {
        float v = swb[j];
        if (v > m1) { m2 = m1; m1 = v; }
        else if (v > m2) { m2 = v; }
    }
#pragma unroll
    for (int off = 1; off <= 2; off <<= 1) {
        float o1 = __shfl_xor_sync(FULL, m1, off);
        float o2 = __shfl_xor_sync(FULL, m2, off);
        float hi = fmaxf(m1, o1);
        float lo = fminf(m1, o1);
        m2 = fmaxf(lo, fmaxf(m2, o2));
        m1 = hi;
    }
    float gscore = m1 + m2;

    const int g = lane >> 2;
    float gsv[8];
#pragma unroll
    for (int j = 0; j < 8; j++) gsv[j] = __shfl_sync(FULL, gscore, j * 4);
    int rank = 0;
#pragma unroll
    for (int j = 0; j < 8; j++)
        rank += (gsv[j] > gsv[g]) || (gsv[j] == gsv[g] && j < g);
    bool gsel = rank < TOPK_GROUP;

    float mv[8];
#pragma unroll
    for (int j = 0; j < 8; j++) mv[j] = gsel ? swb[j] : 0.0f;

    unsigned selmask = 0;
#pragma unroll
    for (int it = 0; it < TOP_K; it++) {
        float bv = mv[0];
        int bj = 0;
#pragma unroll
        for (int j = 1; j < 8; j++)
            if (mv[j] > bv) { bv = mv[j]; bj = j; }
        int bidx = lane * 8 + bj;
#pragma unroll
        for (int off = 16; off > 0; off >>= 1) {
            float ov = __shfl_xor_sync(FULL, bv, off);
            int oi = __shfl_xor_sync(FULL, bidx, off);
            if (ov > bv || (ov == bv && oi < bidx)) { bv = ov; bidx = oi; }
        }
        if ((bidx >> 3) == lane) {
            mv[bidx & 7] = -INFINITY;
            selmask |= 1u << (bidx & 7);
        }
    }

    float ssum = 0.0f;
#pragma unroll
    for (int j = 0; j < 8; j++)
        if ((selmask >> j) & 1) ssum += s[j];
#pragma unroll
    for (int off = 16; off > 0; off >>= 1)
        ssum += __shfl_xor_sync(FULL, ssum, off);
    float inv = ROUTED_SCALE / (ssum + 1e-20f);

    float o[8];
#pragma unroll
    for (int j = 0; j < 8; j++)
        o[j] = ((selmask >> j) & 1) ? s[j] * inv : 0.0f;

    float* orow = out + (size_t)token * N_EXPERTS + lane * 8;
    *(float4*)(orow) = make_float4(o[0], o[1], o[2], o[3]);
    *(float4*)(orow + 4) = make_float4(o[4], o[5], o[6], o[7]);
}

// ---------------------------------------------------------------------------
extern "C" void kernel_launch(void* const* d_in, const int* in_sizes, int n_in,
                              void* d_out, int out_size) {
    const float* X = (const float*)d_in[0];      // [8192, 7168]
    const float* W = (const float*)d_in[1];      // [256, 7168]
    const float* bias = (const float*)d_in[2];   // [256]
    float* out = (float*)d_out;                  // [8192, 256]

    // pre-split W into bf16 h/m/l
    wsplit_kernel<<<(N_EXPERTS * HIDDEN_DIM / 4) / 256, 256>>>(W);

    static bool attr_done = false;
    if (!attr_done) {
        cudaFuncSetAttribute(gate_gemm_mma, cudaFuncAttributeMaxDynamicSharedMemorySize, SMEM_GEMM);
        attr_done = true;
    }
    dim3 ggrid(N_EXPERTS / GBN, T_TOKENS / GBM);   // (4, 64) -> 256 CTAs
    gate_gemm_mma<<<ggrid, 256, SMEM_GEMM>>>(X);

    float* logits_ptr;
    cudaGetSymbolAddress((void**)&logits_ptr, g_logits);
    gate_route_kernel<<<(T_TOKENS * 32) / 256, 256>>>(logits_ptr, bias, out);
}

// round 15
// speedup vs baseline: 1.2469x; 1.0106x over previous
#include <cuda_runtime.h>
#include <cuda_bf16.h>
#include <math.h>
#include <stdint.h>

#define T_TOKENS   8192
#define N_EXPERTS  256
#define HIDDEN_DIM 7168
#define N_GROUP    8
#define TOPK_GROUP 4
#define TOP_K      8
#define ROUTED_SCALE 2.5f

// scratch: fp32 logits + pre-split W (bf16 h/m/l)
__device__ float g_logits[T_TOKENS * N_EXPERTS];
__device__ __nv_bfloat16 g_wh[N_EXPERTS * HIDDEN_DIM];
__device__ __nv_bfloat16 g_wm[N_EXPERTS * HIDDEN_DIM];
__device__ __nv_bfloat16 g_wl[N_EXPERTS * HIDDEN_DIM];

// ---------------------------------------------------------------------------
// helpers
// ---------------------------------------------------------------------------
__device__ __forceinline__ uint32_t smem_to_u32(const void* p) {
    uint32_t a;
    asm("{ .reg .u64 t; cvta.to.shared.u64 t, %1; cvt.u32.u64 %0, t; }" : "=r"(a) : "l"(p));
    return a;
}

// fp32 -> triple bf16 split: h = trunc(x), m = rn(x-h), l = rn(x-h-m).
__device__ __forceinline__ void cvt_split3x4(float4 f, uint2& h, uint2& m, uint2& l) {
    uint32_t xb = __float_as_uint(f.x), yb = __float_as_uint(f.y);
    uint32_t zb = __float_as_uint(f.z), wb = __float_as_uint(f.w);
    h.x = __byte_perm(xb, yb, 0x7632);
    h.y = __byte_perm(zb, wb, 0x7632);
    float r1x = f.x - __uint_as_float(xb & 0xFFFF0000u);
    float r1y = f.y - __uint_as_float(yb & 0xFFFF0000u);
    float r1z = f.z - __uint_as_float(zb & 0xFFFF0000u);
    float r1w = f.w - __uint_as_float(wb & 0xFFFF0000u);
    asm("cvt.rn.bf16x2.f32 %0, %1, %2;" : "=r"(m.x) : "f"(r1y), "f"(r1x));
    asm("cvt.rn.bf16x2.f32 %0, %1, %2;" : "=r"(m.y) : "f"(r1w), "f"(r1z));
    float r2x = r1x - __uint_as_float(m.x << 16);
    float r2y = r1y - __uint_as_float(m.x & 0xFFFF0000u);
    float r2z = r1z - __uint_as_float(m.y << 16);
    float r2w = r1w - __uint_as_float(m.y & 0xFFFF0000u);
    asm("cvt.rn.bf16x2.f32 %0, %1, %2;" : "=r"(l.x) : "f"(r2y), "f"(r2x));
    asm("cvt.rn.bf16x2.f32 %0, %1, %2;" : "=r"(l.y) : "f"(r2w), "f"(r2z));
}

#define LDSM_X4(r, addr) \
    asm volatile("ldmatrix.sync.aligned.m8n8.x4.shared.b16 {%0,%1,%2,%3}, [%4];" \
        : "=r"((r)[0]), "=r"((r)[1]), "=r"((r)[2]), "=r"((r)[3]) : "r"(addr))

#define CP_ASYNC16(dst, src) \
    asm volatile("cp.async.cg.shared.global [%0], [%1], 16;" :: "r"(dst), "l"(src))
#define CP_COMMIT()  asm volatile("cp.async.commit_group;" ::: "memory")
#define CP_WAIT0()   asm volatile("cp.async.wait_group 0;" ::: "memory")

__device__ __forceinline__ void mma16816(float* d, const uint32_t* a, const uint32_t* b) {
    asm volatile(
        "mma.sync.aligned.m16n8k16.row.col.f32.bf16.bf16.f32 "
        "{%0,%1,%2,%3}, {%4,%5,%6,%7}, {%8,%9}, {%0,%1,%2,%3};"
        : "+f"(d[0]), "+f"(d[1]), "+f"(d[2]), "+f"(d[3])
        : "r"(a[0]), "r"(a[1]), "r"(a[2]), "r"(a[3]), "r"(b[0]), "r"(b[1]));
}

__device__ __forceinline__ uint32_t sw128(uint32_t bo) {
    return bo ^ ((bo >> 3) & 0x70u);
}

// ---------------------------------------------------------------------------
// pre-split W into bf16 h/m/l (once per launch; 7.3 MB read)
// ---------------------------------------------------------------------------
__global__ __launch_bounds__(256)
void wsplit_kernel(const float* __restrict__ W) {
    int i = (blockIdx.x * blockDim.x + threadIdx.x) * 4;
    float4 f = *(const float4*)(W + i);
    uint2 h, m, l;
    cvt_split3x4(f, h, m, l);
    *(uint2*)(g_wh + i) = h;
    *(uint2*)(g_wm + i) = m;
    *(uint2*)(g_wl + i) = l;
}

// ---------------------------------------------------------------------------
// GEMM: logits[T,E] = X @ W^T. bf16 mma.sync, 6-pass triple split, fp32 accum.
// mma accumulator drained into FADD fp32 register sum EVERY k16-step.
// CTA 64x64, 256 threads (8 warps: 2m x 4n, warp tile 32x16), 2 CTAs/SM.
// K chunk = 64 bf16 (128B SW128 rows), double-buffered SMEM (2 x 48 KB).
// ---------------------------------------------------------------------------
#define GBM 64
#define GBN 64
#define KC 64
#define CHUNKS (HIDDEN_DIM / KC)   // 112
#define OFF_AH 0
#define OFF_AM 8192
#define OFF_AL 16384
#define OFF_BH 24576
#define OFF_BM 32768
#define OFF_BL 40960
#define STAGE_BYTES 49152
#define SMEM_GEMM (2 * STAGE_BYTES)   // 96 KB -> 2 CTAs/SM

__global__ __launch_bounds__(256, 2)
void gate_gemm_mma(const float* __restrict__ X) {
    extern __shared__ char smem[];
    const uint32_t sbase = smem_to_u32(smem);
    const int tid  = threadIdx.x;
    const int wid  = tid >> 5;
    const int lane = tid & 31;
    const int bm = blockIdx.y * GBM;
    const int bn = blockIdx.x * GBN;
    const int wm = (wid & 1) * 32;    // warp m offset (2-way)
    const int wn = (wid >> 1) * 16;   // warp n offset (4-way)

    // ---- producer addressing: A (LDG fp32 -> split -> STS) ----
    const int rbase = tid >> 4;          // A row base (0..15), rows rbase+16i, i<4
    const int c16   = tid & 15;          // 4 f32 at col c16*4 -> 8 bytes bf16
    uint32_t aswoff[4];
#pragma unroll
    for (int i = 0; i < 4; i++)
        aswoff[i] = sw128((uint32_t)(rbase + 16 * i) * 128u + (uint32_t)c16 * 8u);
    const float* pA = X + (size_t)(bm + rbase) * HIDDEN_DIM + c16 * 4;

    // ---- producer addressing: B (cp.async of pre-split bf16) ----
    const int browB = tid >> 2;          // B row (0..63)
    const int bq    = tid & 3;           // 32B quarter of the 128B row
    uint32_t bswoff[2];
#pragma unroll
    for (int i = 0; i < 2; i++)
        bswoff[i] = sw128((uint32_t)browB * 128u + (uint32_t)bq * 32u + (uint32_t)i * 16u);
    const size_t bOff = (size_t)(bn + browB) * HIDDEN_DIM + bq * 16;
    const __nv_bfloat16* pBh = g_wh + bOff;
    const __nv_bfloat16* pBm = g_wm + bOff;
    const __nv_bfloat16* pBl = g_wl + bOff;

    // ---- ldmatrix addressing (base/mask form, carry-free) ----
    uint32_t aBase[2], aMask[2];
#pragma unroll
    for (int mt = 0; mt < 2; mt++) {
        uint32_t row = (uint32_t)(wm + mt * 16 + (lane & 15));
        aBase[mt] = row * 128u;
        aMask[mt] = (row << 4) & 0x70u;
    }
    const uint32_t aSel = ((uint32_t)lane >> 4) << 4;   // 0 or 16

    uint32_t bBase, bMask;
    {
        const int grp = lane >> 3;
        uint32_t row = (uint32_t)(wn + (lane & 7) + ((grp >> 1) << 3));
        bBase = row * 128u;
        bMask = (row << 4) & 0x70u;
    }
    const uint32_t bSel = (((uint32_t)lane >> 3) & 1) << 4;   // 0 or 16

    float acc[4][4], tot[4][4];
#pragma unroll
    for (int i = 0; i < 4; i++)
#pragma unroll
        for (int j = 0; j < 4; j++) { acc[i][j] = 0.0f; tot[i][j] = 0.0f; }

    // ---- prologue: fill stage 0 with chunk 0 ----
    {
        float4 aR[4];
#pragma unroll
        for (int i = 0; i < 4; i++)
            aR[i] = *(const float4*)(pA + (size_t)i * 16 * HIDDEN_DIM);
        uint32_t dst = sbase;
#pragma unroll
        for (int i = 0; i < 2; i++) {
            CP_ASYNC16(dst + OFF_BH + bswoff[i], (const char*)(pBh + i * 8));
            CP_ASYNC16(dst + OFF_BM + bswoff[i], (const char*)(pBm + i * 8));
            CP_ASYNC16(dst + OFF_BL + bswoff[i], (const char*)(pBl + i * 8));
        }
        CP_COMMIT();
#pragma unroll
        for (int i = 0; i < 4; i++) {
            uint2 h, m, l;
            cvt_split3x4(aR[i], h, m, l);
            *(uint2*)(smem + OFF_AH + aswoff[i]) = h;
            *(uint2*)(smem + OFF_AM + aswoff[i]) = m;
            *(uint2*)(smem + OFF_AL + aswoff[i]) = l;
        }
        CP_WAIT0();
    }
    __syncthreads();

    // ---- main loop ----
    for (int c = 0; c < CHUNKS; c++) {
        const uint32_t stg = sbase + (uint32_t)(c & 1) * STAGE_BYTES;
        float4 aR[4];
        const int kb = (c + 1) * KC;
        if (c + 1 < CHUNKS) {
            // A (c+1) into regs first (front-batched MLP), then B via cp.async
#pragma unroll
            for (int i = 0; i < 4; i++)
                aR[i] = *(const float4*)(pA + kb + (size_t)i * 16 * HIDDEN_DIM);
            uint32_t dst = sbase + (uint32_t)((c + 1) & 1) * STAGE_BYTES;
#pragma unroll
            for (int i = 0; i < 2; i++) {
                CP_ASYNC16(dst + OFF_BH + bswoff[i], (const char*)(pBh + kb + i * 8));
                CP_ASYNC16(dst + OFF_BM + bswoff[i], (const char*)(pBm + kb + i * 8));
                CP_ASYNC16(dst + OFF_BL + bswoff[i], (const char*)(pBl + kb + i * 8));
            }
            CP_COMMIT();
        }

        // MMA over current stage: 4 k16-steps x 6 passes, drain every k-step
#pragma unroll
        for (int ks = 0; ks < 4; ks++) {
            uint32_t ah[2][4], am[2][4], al[2][4], bh[4], bmr[4], bl[4];
            const uint32_t cbA = aSel | (uint32_t)(ks * 32);
            const uint32_t cbB = bSel | (uint32_t)(ks * 32);
#pragma unroll
            for (int mt = 0; mt < 2; mt++) {
                uint32_t off = aBase[mt] + (cbA ^ aMask[mt]);
                LDSM_X4(ah[mt], stg + OFF_AH + off);
                LDSM_X4(am[mt], stg + OFF_AM + off);
                LDSM_X4(al[mt], stg + OFF_AL + off);
            }
            {
                uint32_t off = bBase + (cbB ^ bMask);
                LDSM_X4(bh,  stg + OFF_BH + off);
                LDSM_X4(bmr, stg + OFF_BM + off);
                LDSM_X4(bl,  stg + OFF_BL + off);
            }
#pragma unroll
            for (int mt = 0; mt < 2; mt++) {
#pragma unroll
                for (int nt = 0; nt < 2; nt++) {
                    float* d = acc[mt * 2 + nt];
                    const uint32_t* Bh = &bh[nt * 2];
                    const uint32_t* Bm = &bmr[nt * 2];
                    const uint32_t* Bl = &bl[nt * 2];
                    mma16816(d, ah[mt], Bh);   // h*h
                    mma16816(d, ah[mt], Bm);   // h*m
                    mma16816(d, am[mt], Bh);   // m*h
                    mma16816(d, am[mt], Bm);   // m*m
                    mma16816(d, ah[mt], Bl);   // h*l
                    mma16816(d, al[mt], Bh);   // l*h
                }
            }
            // drain: RN-add this k-step's partial into the running fp32 sum
            // and reset the mma accumulator (chain length 6 -> negligible bias)
#pragma unroll
            for (int i = 0; i < 4; i++)
#pragma unroll
                for (int j = 0; j < 4; j++) {
                    tot[i][j] += acc[i][j];
                    acc[i][j] = 0.0f;
                }
        }

        if (c + 1 < CHUNKS) {
            char* dst = smem + (size_t)((c + 1) & 1) * STAGE_BYTES;
#pragma unroll
            for (int i = 0; i < 4; i++) {
                uint2 h, m, l;
                cvt_split3x4(aR[i], h, m, l);
                *(uint2*)(dst + OFF_AH + aswoff[i]) = h;
                *(uint2*)(dst + OFF_AM + aswoff[i]) = m;
                *(uint2*)(dst + OFF_AL + aswoff[i]) = l;
            }
            CP_WAIT0();
            __syncthreads();
        }
    }

    // ---- epilogue: write fp32 logits ----
    const int crow = lane >> 2;
    const int ccol = (lane & 3) * 2;
#pragma unroll
    for (int mt = 0; mt < 2; mt++) {
#pragma unroll
        for (int nt = 0; nt < 2; nt++) {
            float* p = g_logits + (size_t)(bm + wm + mt * 16 + crow) * N_EXPERTS
                                + bn + wn + nt * 8 + ccol;
            *(float2*)p = make_float2(tot[mt * 2 + nt][0], tot[mt * 2 + nt][1]);
            *(float2*)(p + 8 * N_EXPERTS) = make_float2(tot[mt * 2 + nt][2], tot[mt * 2 + nt][3]);
        }
    }
}

// ---------------------------------------------------------------------------
// Routing: one warp per token. lane l owns experts [l*8, l*8+8); group g = l/4.
// ---------------------------------------------------------------------------
__global__ __launch_bounds__(256)
void gate_route_kernel(const float* __restrict__ logits,
                       const float* __restrict__ bias,
                       float* __restrict__ out) {
    const unsigned FULL = 0xFFFFFFFFu;
    int token = (blockIdx.x * blockDim.x + threadIdx.x) >> 5;
    int lane = threadIdx.x & 31;
    if (token >= T_TOKENS) return;

    const float* row = logits + (size_t)token * N_EXPERTS;
    float4 l0 = *(const float4*)(row + lane * 8);
    float4 l1 = *(const float4*)(row + lane * 8 + 4);
    float4 c0 = *(const float4*)(bias + lane * 8);
    float4 c1 = *(const float4*)(bias + lane * 8 + 4);

    float lg[8] = {l0.x, l0.y, l0.z, l0.w, l1.x, l1.y, l1.z, l1.w};
    float bi[8] = {c0.x, c0.y, c0.z, c0.w, c1.x, c1.y, c1.z, c1.w};
    float s[8], swb[8];
#pragma unroll
    for (int j = 0; j < 8; j++) {
        s[j] = 1.0f / (1.0f + expf(-lg[j]));
        swb[j] = s[j] + bi[j];
    }

    float m1 = -INFINITY, m2 = -INFINITY;
#pragma unroll
    for (int j = 0; j < 8; j++) {
        float v = swb[j];
        if (v > m1) { m2 = m1; m1 = v; }
        else if (v > m2) { m2 = v; }
    }
#pragma unroll
    for (int off = 1; off <= 2; off <<= 1) {
        float o1 = __shfl_xor_sync(FULL, m1, off);
        float o2 = __shfl_xor_sync(FULL, m2, off);
        float hi = fmaxf(m1, o1);
        float lo = fminf(m1, o1);
        m2 = fmaxf(lo, fmaxf(m2, o2));
        m1 = hi;
    }
    float gscore = m1 + m2;

    const int g = lane >> 2;
    float gsv[8];
#pragma unroll
    for (int j = 0; j < 8; j++) gsv[j] = __shfl_sync(FULL, gscore, j * 4);
    int rank = 0;
#pragma unroll
    for (int j = 0; j < 8; j++)
        rank += (gsv[j] > gsv[g]) || (gsv[j] == gsv[g] && j < g);
    bool gsel = rank < TOPK_GROUP;

    float mv[8];
#pragma unroll
    for (int j = 0; j < 8; j++) mv[j] = gsel ? swb[j] : 0.0f;

    unsigned selmask = 0;
#pragma unroll
    for (int it = 0; it < TOP_K; it++) {
        float bv = mv[0];
        int bj = 0;
#pragma unroll
        for (int j = 1; j < 8; j++)
            if (mv[j] > bv) { bv = mv[j]; bj = j; }
        int bidx = lane * 8 + bj;
#pragma unroll
        for (int off = 16; off > 0; off >>= 1) {
            float ov = __shfl_xor_sync(FULL, bv, off);
            int oi = __shfl_xor_sync(FULL, bidx, off);
            if (ov > bv || (ov == bv && oi < bidx)) { bv = ov; bidx = oi; }
        }
        if ((bidx >> 3) == lane) {
            mv[bidx & 7] = -INFINITY;
            selmask |= 1u << (bidx & 7);
        }
    }

    float ssum = 0.0f;
#pragma unroll
    for (int j = 0; j < 8; j++)
        if ((selmask >> j) & 1) ssum += s[j];
#pragma unroll
    for (int off = 16; off > 0; off >>= 1)
        ssum += __shfl_xor_sync(FULL, ssum, off);
    float inv = ROUTED_SCALE / (ssum + 1e-20f);

    float o[8];
#pragma unroll
    for (int j = 0; j < 8; j++)
        o[j] = ((selmask >> j) & 1) ? s[j] * inv : 0.0f;

    float* orow = out + (size_t)token * N_EXPERTS + lane * 8;
    *(float4*)(orow) = make_float4(o[0], o[1], o[2], o[3]);
    *(float4*)(orow + 4) = make_float4(o[4], o[5], o[6], o[7]);
}

// ---------------------------------------------------------------------------
extern "C" void kernel_launch(void* const* d_in, const int* in_sizes, int n_in,
                              void* d_out, int out_size) {
    const float* X = (const float*)d_in[0];      // [8192, 7168]
    const float* W = (const float*)d_in[1];      // [256, 7168]
    const float* bias = (const float*)d_in[2];   // [256]
    float* out = (float*)d_out;                  // [8192, 256]

    // pre-split W into bf16 h/m/l
    wsplit_kernel<<<(N_EXPERTS * HIDDEN_DIM / 4) / 256, 256>>>(W);

    static bool attr_done = false;
    if (!attr_done) {
        cudaFuncSetAttribute(gate_gemm_mma, cudaFuncAttributeMaxDynamicSharedMemorySize, SMEM_GEMM);
        attr_done = true;
    }
    dim3 ggrid(N_EXPERTS / GBN, T_TOKENS / GBM);   // (4, 128) -> 512 CTAs
    gate_gemm_mma<<<ggrid, 256, SMEM_GEMM>>>(X);

    float* logits_ptr;
    cudaGetSymbolAddress((void**)&logits_ptr, g_logits);
    gate_route_kernel<<<(T_TOKENS * 32) / 256, 256>>>(logits_ptr, bias, out);
}

// round 17
// speedup vs baseline: 2.0012x; 1.6050x over previous
#include <cuda_runtime.h>
#include <cuda_fp16.h>
#include <math.h>
#include <stdint.h>

#define T_TOKENS   8192
#define N_EXPERTS  256
#define HIDDEN_DIM 7168
#define N_GROUP    8
#define TOPK_GROUP 4
#define TOP_K      8
#define ROUTED_SCALE 2.5f
#define DESCALE 9.5367431640625e-07f   // 2^-20

// scratch: fp32 logits + pre-split W (fp16 h/m, scaled by 2^10)
__device__ float g_logits[T_TOKENS * N_EXPERTS];
__device__ __half g_wh[N_EXPERTS * HIDDEN_DIM];
__device__ __half g_wm[N_EXPERTS * HIDDEN_DIM];

// ---------------------------------------------------------------------------
// helpers
// ---------------------------------------------------------------------------
__device__ __forceinline__ uint32_t smem_to_u32(const void* p) {
    uint32_t a;
    asm("{ .reg .u64 t; cvta.to.shared.u64 t, %1; cvt.u32.u64 %0, t; }" : "=r"(a) : "l"(p));
    return a;
}

// fp32 -> scaled fp16 2-term split: s = x*1024; h = rn_f16(s), m = rn_f16(s - h).
// Packed f16x2 pairs (x in low half, y in high half).
__device__ __forceinline__ void cvt_split2h(float4 f, uint2& h, uint2& m) {
    float sx = f.x * 1024.0f, sy = f.y * 1024.0f;
    float sz = f.z * 1024.0f, sw = f.w * 1024.0f;
    asm("cvt.rn.f16x2.f32 %0, %1, %2;" : "=r"(h.x) : "f"(sy), "f"(sx));
    asm("cvt.rn.f16x2.f32 %0, %1, %2;" : "=r"(h.y) : "f"(sw), "f"(sz));
    float hx, hy, hz, hw;
    asm("{.reg .f16 lo, hi; mov.b32 {lo, hi}, %2; cvt.f32.f16 %0, lo; cvt.f32.f16 %1, hi;}"
        : "=f"(hx), "=f"(hy) : "r"(h.x));
    asm("{.reg .f16 lo, hi; mov.b32 {lo, hi}, %2; cvt.f32.f16 %0, lo; cvt.f32.f16 %1, hi;}"
        : "=f"(hz), "=f"(hw) : "r"(h.y));
    asm("cvt.rn.f16x2.f32 %0, %1, %2;" : "=r"(m.x) : "f"(sy - hy), "f"(sx - hx));
    asm("cvt.rn.f16x2.f32 %0, %1, %2;" : "=r"(m.y) : "f"(sw - hw), "f"(sz - hz));
}

#define LDSM_X4(r, addr) \
    asm volatile("ldmatrix.sync.aligned.m8n8.x4.shared.b16 {%0,%1,%2,%3}, [%4];" \
        : "=r"((r)[0]), "=r"((r)[1]), "=r"((r)[2]), "=r"((r)[3]) : "r"(addr))

#define CP_ASYNC16(dst, src) \
    asm volatile("cp.async.cg.shared.global [%0], [%1], 16;" :: "r"(dst), "l"(src))
#define CP_COMMIT()  asm volatile("cp.async.commit_group;" ::: "memory")
#define CP_WAIT0()   asm volatile("cp.async.wait_group 0;" ::: "memory")

__device__ __forceinline__ void mma16816(float* d, const uint32_t* a, const uint32_t* b) {
    asm volatile(
        "mma.sync.aligned.m16n8k16.row.col.f32.f16.f16.f32 "
        "{%0,%1,%2,%3}, {%4,%5,%6,%7}, {%8,%9}, {%0,%1,%2,%3};"
        : "+f"(d[0]), "+f"(d[1]), "+f"(d[2]), "+f"(d[3])
        : "r"(a[0]), "r"(a[1]), "r"(a[2]), "r"(a[3]), "r"(b[0]), "r"(b[1]));
}

__device__ __forceinline__ uint32_t sw128(uint32_t bo) {
    return bo ^ ((bo >> 3) & 0x70u);
}

// ---------------------------------------------------------------------------
// pre-split W into scaled fp16 h/m (once per launch; 7.3 MB read)
// ---------------------------------------------------------------------------
__global__ __launch_bounds__(256)
void wsplit_kernel(const float* __restrict__ W) {
    int i = (blockIdx.x * blockDim.x + threadIdx.x) * 4;
    float4 f = *(const float4*)(W + i);
    uint2 h, m;
    cvt_split2h(f, h, m);
    *(uint2*)(g_wh + i) = h;
    *(uint2*)(g_wm + i) = m;
}

// ---------------------------------------------------------------------------
// GEMM: logits[T,E] = X @ W^T. fp16 mma.sync, 3-pass scaled split, fp32 accum.
// mma accumulator drained into FADD fp32 register sum every 2 k16-steps
// (HMMA chain length 6 - validated bias-safe in R14).
// CTA 64x64, 256 threads (8 warps: 2m x 4n, warp tile 32x16), 2 CTAs/SM.
// K chunk = 64 fp16 (128B SW128 rows), double-buffered SMEM (2 x 32 KB).
// ---------------------------------------------------------------------------
#define GBM 64
#define GBN 64
#define KC 64
#define CHUNKS (HIDDEN_DIM / KC)   // 112
#define OFF_AH 0
#define OFF_AM 8192
#define OFF_BH 16384
#define OFF_BM 24576
#define STAGE_BYTES 32768
#define SMEM_GEMM (2 * STAGE_BYTES)   // 64 KB -> 2 CTAs/SM

__global__ __launch_bounds__(256, 2)
void gate_gemm_mma(const float* __restrict__ X) {
    extern __shared__ char smem[];
    const uint32_t sbase = smem_to_u32(smem);
    const int tid  = threadIdx.x;
    const int wid  = tid >> 5;
    const int lane = tid & 31;
    const int bm = blockIdx.y * GBM;
    const int bn = blockIdx.x * GBN;
    const int wm = (wid & 1) * 32;    // warp m offset (2-way)
    const int wn = (wid >> 1) * 16;   // warp n offset (4-way)

    // ---- producer addressing: A (LDG fp32 -> split -> STS) ----
    const int rbase = tid >> 4;          // A row base (0..15), rows rbase+16i, i<4
    const int c16   = tid & 15;          // 4 f32 at col c16*4 -> 8 bytes fp16
    uint32_t aswoff[4];
#pragma unroll
    for (int i = 0; i < 4; i++)
        aswoff[i] = sw128((uint32_t)(rbase + 16 * i) * 128u + (uint32_t)c16 * 8u);
    const float* pA = X + (size_t)(bm + rbase) * HIDDEN_DIM + c16 * 4;

    // ---- producer addressing: B (cp.async of pre-split fp16) ----
    const int browB = tid >> 2;          // B row (0..63)
    const int bq    = tid & 3;           // 32B quarter of the 128B row
    uint32_t bswoff[2];
#pragma unroll
    for (int i = 0; i < 2; i++)
        bswoff[i] = sw128((uint32_t)browB * 128u + (uint32_t)bq * 32u + (uint32_t)i * 16u);
    const size_t bOff = (size_t)(bn + browB) * HIDDEN_DIM + bq * 16;
    const __half* pBh = g_wh + bOff;
    const __half* pBm = g_wm + bOff;

    // ---- ldmatrix addressing (base/mask form, carry-free) ----
    uint32_t aBase[2], aMask[2];
#pragma unroll
    for (int mt = 0; mt < 2; mt++) {
        uint32_t row = (uint32_t)(wm + mt * 16 + (lane & 15));
        aBase[mt] = row * 128u;
        aMask[mt] = (row << 4) & 0x70u;
    }
    const uint32_t aSel = ((uint32_t)lane >> 4) << 4;   // 0 or 16

    uint32_t bBase, bMask;
    {
        const int grp = lane >> 3;
        uint32_t row = (uint32_t)(wn + (lane & 7) + ((grp >> 1) << 3));
        bBase = row * 128u;
        bMask = (row << 4) & 0x70u;
    }
    const uint32_t bSel = (((uint32_t)lane >> 3) & 1) << 4;   // 0 or 16

    float acc[4][4], tot[4][4];
#pragma unroll
    for (int i = 0; i < 4; i++)
#pragma unroll
        for (int j = 0; j < 4; j++) { acc[i][j] = 0.0f; tot[i][j] = 0.0f; }

    // ---- prologue: fill stage 0 with chunk 0 ----
    {
        float4 aR[4];
#pragma unroll
        for (int i = 0; i < 4; i++)
            aR[i] = *(const float4*)(pA + (size_t)i * 16 * HIDDEN_DIM);
        uint32_t dst = sbase;
#pragma unroll
        for (int i = 0; i < 2; i++) {
            CP_ASYNC16(dst + OFF_BH + bswoff[i], (const char*)(pBh + i * 8));
            CP_ASYNC16(dst + OFF_BM + bswoff[i], (const char*)(pBm + i * 8));
        }
        CP_COMMIT();
#pragma unroll
        for (int i = 0; i < 4; i++) {
            uint2 h, m;
            cvt_split2h(aR[i], h, m);
            *(uint2*)(smem + OFF_AH + aswoff[i]) = h;
            *(uint2*)(smem + OFF_AM + aswoff[i]) = m;
        }
        CP_WAIT0();
    }
    __syncthreads();

    // ---- main loop ----
    for (int c = 0; c < CHUNKS; c++) {
        const uint32_t stg = sbase + (uint32_t)(c & 1) * STAGE_BYTES;
        float4 aR[4];
        const int kb = (c + 1) * KC;
        if (c + 1 < CHUNKS) {
            // A (c+1) into regs first (front-batched MLP), then B via cp.async
#pragma unroll
            for (int i = 0; i < 4; i++)
                aR[i] = *(const float4*)(pA + kb + (size_t)i * 16 * HIDDEN_DIM);
            uint32_t dst = sbase + (uint32_t)((c + 1) & 1) * STAGE_BYTES;
#pragma unroll
            for (int i = 0; i < 2; i++) {
                CP_ASYNC16(dst + OFF_BH + bswoff[i], (const char*)(pBh + kb + i * 8));
                CP_ASYNC16(dst + OFF_BM + bswoff[i], (const char*)(pBm + kb + i * 8));
            }
            CP_COMMIT();
        }

        // MMA over current stage: 4 k16-steps x 3 passes, drain every 2 k-steps
#pragma unroll
        for (int ks = 0; ks < 4; ks++) {
            uint32_t ah[2][4], am[2][4], bh[4], bmr[4];
            const uint32_t cbA = aSel | (uint32_t)(ks * 32);
            const uint32_t cbB = bSel | (uint32_t)(ks * 32);
#pragma unroll
            for (int mt = 0; mt < 2; mt++) {
                uint32_t off = aBase[mt] + (cbA ^ aMask[mt]);
                LDSM_X4(ah[mt], stg + OFF_AH + off);
                LDSM_X4(am[mt], stg + OFF_AM + off);
            }
            {
                uint32_t off = bBase + (cbB ^ bMask);
                LDSM_X4(bh,  stg + OFF_BH + off);
                LDSM_X4(bmr, stg + OFF_BM + off);
            }
#pragma unroll
            for (int mt = 0; mt < 2; mt++) {
#pragma unroll
                for (int nt = 0; nt < 2; nt++) {
                    float* d = acc[mt * 2 + nt];
                    const uint32_t* Bh = &bh[nt * 2];
                    const uint32_t* Bm = &bmr[nt * 2];
                    mma16816(d, ah[mt], Bh);   // h*h
                    mma16816(d, ah[mt], Bm);   // h*m
                    mma16816(d, am[mt], Bh);   // m*h
                }
            }
            // drain every 2 k-steps: chain length 6 (validated bias-safe)
            if (ks & 1) {
#pragma unroll
                for (int i = 0; i < 4; i++)
#pragma unroll
                    for (int j = 0; j < 4; j++) {
                        tot[i][j] += acc[i][j];
                        acc[i][j] = 0.0f;
                    }
            }
        }

        if (c + 1 < CHUNKS) {
            char* dst = smem + (size_t)((c + 1) & 1) * STAGE_BYTES;
#pragma unroll
            for (int i = 0; i < 4; i++) {
                uint2 h, m;
                cvt_split2h(aR[i], h, m);
                *(uint2*)(dst + OFF_AH + aswoff[i]) = h;
                *(uint2*)(dst + OFF_AM + aswoff[i]) = m;
            }
            CP_WAIT0();
            __syncthreads();
        }
    }

    // ---- epilogue: descale (2^-20, exact) and write fp32 logits ----
    const int crow = lane >> 2;
    const int ccol = (lane & 3) * 2;
#pragma unroll
    for (int mt = 0; mt < 2; mt++) {
#pragma unroll
        for (int nt = 0; nt < 2; nt++) {
            float* p = g_logits + (size_t)(bm + wm + mt * 16 + crow) * N_EXPERTS
                                + bn + wn + nt * 8 + ccol;
            const float* t = tot[mt * 2 + nt];
            *(float2*)p = make_float2(t[0] * DESCALE, t[1] * DESCALE);
            *(float2*)(p + 8 * N_EXPERTS) = make_float2(t[2] * DESCALE, t[3] * DESCALE);
        }
    }
}

// ---------------------------------------------------------------------------
// Routing: one warp per token. lane l owns experts [l*8, l*8+8); group g = l/4.
// ---------------------------------------------------------------------------
__global__ __launch_bounds__(256)
void gate_route_kernel(const float* __restrict__ logits,
                       const float* __restrict__ bias,
                       float* __restrict__ out) {
    const unsigned FULL = 0xFFFFFFFFu;
    int token = (blockIdx.x * blockDim.x + threadIdx.x) >> 5;
    int lane = threadIdx.x & 31;
    if (token >= T_TOKENS) return;

    const float* row = logits + (size_t)token * N_EXPERTS;
    float4 l0 = *(const float4*)(row + lane * 8);
    float4 l1 = *(const float4*)(row + lane * 8 + 4);
    float4 c0 = *(const float4*)(bias + lane * 8);
    float4 c1 = *(const float4*)(bias + lane * 8 + 4);

    float lg[8] = {l0.x, l0.y, l0.z, l0.w, l1.x, l1.y, l1.z, l1.w};
    float bi[8] = {c0.x, c0.y, c0.z, c0.w, c1.x, c1.y, c1.z, c1.w};
    float s[8], swb[8];
#pragma unroll
    for (int j = 0; j < 8; j++) {
        s[j] = 1.0f / (1.0f + expf(-lg[j]));
        swb[j] = s[j] + bi[j];
    }

    float m1 = -INFINITY, m2 = -INFINITY;
#pragma unroll
    for (int j = 0; j < 8; j++) {
        float v = swb[j];
        if (v > m1) { m2 = m1; m1 = v; }
        else if (v > m2) { m2 = v; }
    }
#pragma unroll
    for (int off = 1; off <= 2; off <<= 1) {
        float o1 = __shfl_xor_sync(FULL, m1, off);
        float o2 = __shfl_xor_sync(FULL, m2, off);
        float hi = fmaxf(m1, o1);
        float lo = fminf(m1, o1);
        m2 = fmaxf(lo, fmaxf(m2, o2));
        m1 = hi;
    }
    float gscore = m1 + m2;

    const int g = lane >> 2;
    float gsv[8];
#pragma unroll
    for (int j = 0; j < 8; j++) gsv[j] = __shfl_sync(FULL, gscore, j * 4);
    int rank = 0;
#pragma unroll
    for (int j = 0; j < 8; j++)
        rank += (gsv[j] > gsv[g]) || (gsv[j] == gsv[g] && j < g);
    bool gsel = rank < TOPK_GROUP;

    float mv[8];
#pragma unroll
    for (int j = 0; j < 8; j++) mv[j] = gsel ? swb[j] : 0.0f;

    unsigned selmask = 0;
#pragma unroll
    for (int it = 0; it < TOP_K; it++) {
        float bv = mv[0];
        int bj = 0;
#pragma unroll
        for (int j = 1; j < 8; j++)
            if (mv[j] > bv) { bv = mv[j]; bj = j; }
        int bidx = lane * 8 + bj;
#pragma unroll
        for (int off = 16; off > 0; off >>= 1) {
            float ov = __shfl_xor_sync(FULL, bv, off);
            int oi = __shfl_xor_sync(FULL, bidx, off);
            if (ov > bv || (ov == bv && oi < bidx)) { bv = ov; bidx = oi; }
        }
        if ((bidx >> 3) == lane) {
            mv[bidx & 7] = -INFINITY;
            selmask |= 1u << (bidx & 7);
        }
    }

    float ssum = 0.0f;
#pragma unroll
    for (int j = 0; j < 8; j++)
        if ((selmask >> j) & 1) ssum += s[j];
#pragma unroll
    for (int off = 16; off > 0; off >>= 1)
        ssum += __shfl_xor_sync(FULL, ssum, off);
    float inv = ROUTED_SCALE / (ssum + 1e-20f);

    float o[8];
#pragma unroll
    for (int j = 0; j < 8; j++)
        o[j] = ((selmask >> j) & 1) ? s[j] * inv : 0.0f;

    float* orow = out + (size_t)token * N_EXPERTS + lane * 8;
    *(float4*)(orow) = make_float4(o[0], o[1], o[2], o[3]);
    *(float4*)(orow + 4) = make_float4(o[4], o[5], o[6], o[7]);
}

// ---------------------------------------------------------------------------
extern "C" void kernel_launch(void* const* d_in, const int* in_sizes, int n_in,
                              void* d_out, int out_size) {
    const float* X = (const float*)d_in[0];      // [8192, 7168]
    const float* W = (const float*)d_in[1];      // [256, 7168]
    const float* bias = (const float*)d_in[2];   // [256]
    float* out = (float*)d_out;                  // [8192, 256]

    // pre-split W into scaled fp16 h/m
    wsplit_kernel<<<(N_EXPERTS * HIDDEN_DIM / 4) / 256, 256>>>(W);

    cudaFuncSetAttribute(gate_gemm_mma, cudaFuncAttributeMaxDynamicSharedMemorySize, SMEM_GEMM);
    dim3 ggrid(N_EXPERTS / GBN, T_TOKENS / GBM);   // (4, 128) -> 512 CTAs
    gate_gemm_mma<<<ggrid, 256, SMEM_GEMM>>>(X);

    float* logits_ptr;
    cudaGetSymbolAddress((void**)&logits_ptr, g_logits);
    gate_route_kernel<<<(T_TOKENS * 32) / 256, 256>>>(logits_ptr, bias, out);
}